// round 9
// baseline (speedup 1.0000x reference)
#include <cuda_runtime.h>
#include <cstdint>
#include <cstddef>

#define TSIZE (1u << 18)
#define TMASK (TSIZE - 1u)
#define NLEV 16
#define P1 2654435761u
#define P2 805459861u

#define NBUCK (1u << 18)   // 64^3 buckets
#define NMAX (1 << 21)

// Device-global scratch (no allocation).
// g_count: zero at module load; scan_part re-zeroes after consuming, so it is
// zero at the start of every kernel_launch invocation (incl. graph replays).
__device__ __align__(16) float2 g_hash[15u * TSIZE];
__device__ __align__(16) float2 g_dense[16 * 16 * 16];
__device__ unsigned g_count[NBUCK];
__device__ unsigned g_cursor[NBUCK];
__device__ unsigned g_bsum[256];
__device__ unsigned g_boff[256];
__device__ float4   g_buf[NMAX];           // bucketed points {x,y,z,idx}

__device__ __forceinline__ int bucket_of(float cx, float cy, float cz) {
    int bx = min(63, max(0, (int)((cx + 1.0f) * 32.0f)));
    int by = min(63, max(0, (int)((cy + 1.0f) * 32.0f)));
    int bz = min(63, max(0, (int)((cz + 1.0f) * 32.0f)));
    return (bx * 64 + by) * 64 + bz;
}

// ---------------------------------------------------------------------------
// Fused prep: repack tables + histogram points (g_count pre-zeroed).
// ---------------------------------------------------------------------------
__global__ void prep_kernel(const float* __restrict__ dense,
                            const float* __restrict__ hash,
                            const float* __restrict__ coords, int N) {
    unsigned i = blockIdx.x * blockDim.x + threadIdx.x;
    if (i < 15u * TSIZE) {
        unsigned l = i >> 18;
        unsigned t = i & TMASK;
        const float* base = hash + (size_t)l * (2u * TSIZE);
        g_hash[i] = make_float2(base[t], base[TSIZE + t]);
    }
    if (i < 4096u)
        g_dense[i] = make_float2(dense[i], dense[4096u + i]);
    if (i < (unsigned)N) {
        int b = bucket_of(coords[3 * i], coords[3 * i + 1], coords[3 * i + 2]);
        atomicAdd(&g_count[b], 1u);
    }
}

// ---------------------------------------------------------------------------
// Parallel scan over 262144 counters (self-cleaning).
// ---------------------------------------------------------------------------
__global__ __launch_bounds__(1024)
void scan_part_kernel() {
    __shared__ unsigned sh[1024];
    const int b = blockIdx.x, t = threadIdx.x;
    const unsigned gi = b * 1024 + t;
    const unsigned v = g_count[gi];
    g_count[gi] = 0u;                      // self-clean for next invocation
    sh[t] = v;
    __syncthreads();
    for (int off = 1; off < 1024; off <<= 1) {
        unsigned u = 0;
        if (t >= off) u = sh[t - off];
        __syncthreads();
        sh[t] += u;
        __syncthreads();
    }
    g_cursor[gi] = sh[t] - v;
    if (t == 1023) g_bsum[b] = sh[t];
}

__global__ __launch_bounds__(256)
void scan_top_kernel() {
    __shared__ unsigned sh[256];
    const int t = threadIdx.x;
    const unsigned v = g_bsum[t];
    sh[t] = v;
    __syncthreads();
    for (int off = 1; off < 256; off <<= 1) {
        unsigned u = 0;
        if (t >= off) u = sh[t - off];
        __syncthreads();
        sh[t] += u;
        __syncthreads();
    }
    g_boff[t] = sh[t] - v;
}

__global__ __launch_bounds__(1024)
void scan_apply_kernel() {
    const unsigned i = blockIdx.x * 1024u + threadIdx.x;
    g_cursor[i] += g_boff[blockIdx.x];
}

__global__ void scatter_kernel(const float* __restrict__ coords, int N) {
    int i = blockIdx.x * blockDim.x + threadIdx.x;
    if (i >= N) return;
    float x = coords[3 * i], y = coords[3 * i + 1], z = coords[3 * i + 2];
    int b = bucket_of(x, y, z);
    unsigned slot = atomicAdd(&g_cursor[b], 1u);
    g_buf[slot] = make_float4(x, y, z, __int_as_float(i));
}

// ---------------------------------------------------------------------------
// Shared per-level interpolation body (hashed levels).
// ---------------------------------------------------------------------------
__device__ __forceinline__ void hash_level(float cx, float cy, float cz,
                                           int res, const float2* __restrict__ tbl,
                                           float& a0, float& a1) {
    const float rm1 = (float)(res - 1);
    float px = fminf(fmaxf((cx + 1.0f) * 0.5f * rm1, 0.0f), rm1);
    float py = fminf(fmaxf((cy + 1.0f) * 0.5f * rm1, 0.0f), rm1);
    float pz = fminf(fmaxf((cz + 1.0f) * 0.5f * rm1, 0.0f), rm1);

    int ix0 = (int)px;  float wx = px - (float)ix0;
    int iy0 = (int)py;  float wy = py - (float)iy0;
    int iz0 = (int)pz;  float wz = pz - (float)iz0;
    int ix1 = min(ix0 + 1, res - 1);
    int iy1 = min(iy0 + 1, res - 1);
    int iz1 = min(iz0 + 1, res - 1);

    const float wxv0 = 1.0f - wx, wxv1 = wx;
    const float wyv0 = 1.0f - wy, wyv1 = wy;
    const float wzv0 = 1.0f - wz, wzv1 = wz;

    const unsigned hx0 = (unsigned)ix0;  // prime 1
    const unsigned hx1 = (unsigned)ix1;
    const unsigned hy0 = (unsigned)iy0 * P1;
    const unsigned hy1 = (unsigned)iy1 * P1;
    const unsigned hz0 = (unsigned)iz0 * P2;
    const unsigned hz1 = (unsigned)iz1 * P2;

    float2 f[8];
    float  wg[8];
#pragma unroll
    for (int c = 0; c < 8; ++c) {
        const unsigned h = (((c & 4) ? hx1 : hx0) ^
                            ((c & 2) ? hy1 : hy0) ^
                            ((c & 1) ? hz1 : hz0)) & TMASK;
        f[c] = __ldg(&tbl[h]);
        wg[c] = ((c & 4) ? wxv1 : wxv0) *
                ((c & 2) ? wyv1 : wyv0) *
                ((c & 1) ? wzv1 : wzv0);
    }
    a0 = 0.0f; a1 = 0.0f;
#pragma unroll
    for (int c = 0; c < 8; ++c) {
        a0 = fmaf(f[c].x, wg[c], a0);
        a1 = fmaf(f[c].y, wg[c], a1);
    }
}

// ---------------------------------------------------------------------------
// encode_coarse: levels 0..11 in bucket order -> floats 0..23 of each row.
// ---------------------------------------------------------------------------
__global__ __launch_bounds__(256)
void encode_coarse_kernel(float* __restrict__ out, int N) {
    int i = blockIdx.x * blockDim.x + threadIdx.x;
    if (i >= N) return;

    const float4 pt = g_buf[i];
    const float cx = pt.x, cy = pt.y, cz = pt.z;
    const int idx = __float_as_int(pt.w);
    float4* __restrict__ out4 = reinterpret_cast<float4*>(out + (size_t)idx * 32);

    constexpr int RES[12] = {16, 20, 25, 32, 40, 50, 64, 80, 101, 128, 161, 203};

    float4 obuf = make_float4(0.f, 0.f, 0.f, 0.f);

    // Level 0: dense grid.
    {
        const int res = 16;
        const float rm1 = 15.0f;
        float px = fminf(fmaxf((cx + 1.0f) * 0.5f * rm1, 0.0f), rm1);
        float py = fminf(fmaxf((cy + 1.0f) * 0.5f * rm1, 0.0f), rm1);
        float pz = fminf(fmaxf((cz + 1.0f) * 0.5f * rm1, 0.0f), rm1);
        int ix0 = (int)px;  float wx = px - (float)ix0;
        int iy0 = (int)py;  float wy = py - (float)iy0;
        int iz0 = (int)pz;  float wz = pz - (float)iz0;
        int ix1 = min(ix0 + 1, res - 1);
        int iy1 = min(iy0 + 1, res - 1);
        int iz1 = min(iz0 + 1, res - 1);
        const float wxv0 = 1.0f - wx, wxv1 = wx;
        const float wyv0 = 1.0f - wy, wyv1 = wy;
        const float wzv0 = 1.0f - wz, wzv1 = wz;
        float a0 = 0.f, a1 = 0.f;
#pragma unroll
        for (int c = 0; c < 8; ++c) {
            const int xi = (c & 4) ? ix1 : ix0;
            const int yi = (c & 2) ? iy1 : iy0;
            const int zi = (c & 1) ? iz1 : iz0;
            const float2 f = __ldg(&g_dense[(xi * 16 + yi) * 16 + zi]);
            const float w = ((c & 4) ? wxv1 : wxv0) *
                            ((c & 2) ? wyv1 : wyv0) *
                            ((c & 1) ? wzv1 : wzv0);
            a0 = fmaf(f.x, w, a0);
            a1 = fmaf(f.y, w, a1);
        }
        obuf.x = a0; obuf.y = a1;
    }

#pragma unroll
    for (int l = 1; l < 12; ++l) {
        float a0, a1;
        hash_level(cx, cy, cz, RES[l], g_hash + (size_t)(l - 1) * TSIZE, a0, a1);
        if ((l & 1) == 0) {
            obuf.x = a0; obuf.y = a1;
        } else {
            obuf.z = a0; obuf.w = a1;
            out4[l >> 1] = obuf;
        }
    }
}

// ---------------------------------------------------------------------------
// encode_fine: levels 12..15 in ORIGINAL order -> floats 24..31 of each row.
// Depends only on prep (g_hash); runs concurrently with scan/scatter.
// ---------------------------------------------------------------------------
__global__ __launch_bounds__(256)
void encode_fine_kernel(const float* __restrict__ coords,
                        float* __restrict__ out, int N) {
    int i = blockIdx.x * blockDim.x + threadIdx.x;
    if (i >= N) return;

    const float cx = __ldg(&coords[3 * i + 0]);
    const float cy = __ldg(&coords[3 * i + 1]);
    const float cz = __ldg(&coords[3 * i + 2]);
    float4* __restrict__ out4 = reinterpret_cast<float4*>(out + (size_t)i * 32);

    constexpr int RES[4] = {256, 322, 406, 512};

    float4 obuf;
#pragma unroll
    for (int k = 0; k < 4; ++k) {
        float a0, a1;
        hash_level(cx, cy, cz, RES[k], g_hash + (size_t)(k + 11) * TSIZE, a0, a1);
        if ((k & 1) == 0) {
            obuf.x = a0; obuf.y = a1;
        } else {
            obuf.z = a0; obuf.w = a1;
            out4[6 + (k >> 1)] = obuf;
        }
    }
}

// ---------------------------------------------------------------------------
// kernel_launch: prep -> fork{ encode_fine } || { scan(3), scatter,
//                encode_coarse } -> join.  Streams/events created lazily on
// the first (uncaptured correctness) call; capture sees only launches+events.
// ---------------------------------------------------------------------------
extern "C" void kernel_launch(void* const* d_in, const int* in_sizes, int n_in,
                              void* d_out, int out_size) {
    const float* coords = (const float*)d_in[0];
    const float* dense  = (const float*)d_in[1];
    const float* hash   = (const float*)d_in[2];
    float* out = (float*)d_out;

    const int N = in_sizes[0] / 3;
    const int nb = (N + 255) / 256;

    static cudaStream_t s_fine = nullptr;
    static cudaEvent_t ev_prep = nullptr, ev_fine = nullptr;
    if (s_fine == nullptr) {
        cudaStreamCreateWithFlags(&s_fine, cudaStreamNonBlocking);
        cudaEventCreateWithFlags(&ev_prep, cudaEventDisableTiming);
        cudaEventCreateWithFlags(&ev_fine, cudaEventDisableTiming);
    }

    const unsigned prep_total = 15u * TSIZE;
    prep_kernel<<<(prep_total + 255u) / 256u, 256>>>(dense, hash, coords, N);

    // Fork: fine levels don't need the permutation.
    cudaEventRecord(ev_prep, 0);
    cudaStreamWaitEvent(s_fine, ev_prep, 0);
    encode_fine_kernel<<<nb, 256, 0, s_fine>>>(coords, out, N);
    cudaEventRecord(ev_fine, s_fine);

    // Main branch: build permutation, then coarse/mid levels.
    scan_part_kernel<<<NBUCK / 1024, 1024>>>();
    scan_top_kernel<<<1, 256>>>();
    scan_apply_kernel<<<NBUCK / 1024, 1024>>>();
    scatter_kernel<<<nb, 256>>>(coords, N);
    encode_coarse_kernel<<<nb, 256>>>(out, N);

    // Join.
    cudaStreamWaitEvent(0, ev_fine, 0);
}

// round 10
// speedup vs baseline: 1.1566x; 1.1566x over previous
#include <cuda_runtime.h>
#include <cstdint>
#include <cstddef>

#define TSIZE (1u << 18)
#define TMASK (TSIZE - 1u)
#define NLEV 16
#define P1 2654435761u
#define P2 805459861u

#define NBUCK (1u << 18)   // 64^3 buckets
#define NMAX (1 << 21)

// Device-global scratch (no allocation).
// g_count: zero at module load; scan_part re-zeroes after consuming, so it is
// zero at the start of every kernel_launch invocation (incl. graph replays).
__device__ __align__(16) float2 g_hash[15u * TSIZE];
__device__ __align__(16) float2 g_dense[16 * 16 * 16];
__device__ unsigned g_count[NBUCK];
__device__ unsigned g_cursor[NBUCK];
__device__ unsigned g_bsum[256];
__device__ unsigned g_boff[256];
__device__ float4   g_buf[NMAX];           // bucketed points {x,y,z,idx}

__device__ __forceinline__ int bucket_of(float cx, float cy, float cz) {
    int bx = min(63, max(0, (int)((cx + 1.0f) * 32.0f)));
    int by = min(63, max(0, (int)((cy + 1.0f) * 32.0f)));
    int bz = min(63, max(0, (int)((cz + 1.0f) * 32.0f)));
    return (bx * 64 + by) * 64 + bz;
}

// ---------------------------------------------------------------------------
// Repack (stream B): tables -> feature-interleaved float2. 2 entries/thread.
// ---------------------------------------------------------------------------
__global__ void repack_kernel(const float* __restrict__ dense,
                              const float* __restrict__ hash) {
    unsigned i = blockIdx.x * blockDim.x + threadIdx.x;   // entry-pair index
    if (i < 15u * TSIZE / 2u) {
        unsigned l = i / (TSIZE / 2u);
        unsigned t = (i % (TSIZE / 2u)) * 2u;
        const float* base = hash + (size_t)l * (2u * TSIZE);
        const float2 lo = *reinterpret_cast<const float2*>(base + t);
        const float2 hi = *reinterpret_cast<const float2*>(base + TSIZE + t);
        float4 v = make_float4(lo.x, hi.x, lo.y, hi.y);
        *reinterpret_cast<float4*>(&g_hash[l * TSIZE + t]) = v;
    }
    if (i < 4096u)
        g_dense[i] = make_float2(dense[i], dense[4096u + i]);
}

// ---------------------------------------------------------------------------
// Histogram (stream A).
// ---------------------------------------------------------------------------
__global__ void hist_kernel(const float* __restrict__ coords, int N) {
    int i = blockIdx.x * blockDim.x + threadIdx.x;
    if (i >= N) return;
    int b = bucket_of(coords[3 * i], coords[3 * i + 1], coords[3 * i + 2]);
    atomicAdd(&g_count[b], 1u);
}

// Parallel scan (self-cleaning counters).
__global__ __launch_bounds__(1024)
void scan_part_kernel() {
    __shared__ unsigned sh[1024];
    const int b = blockIdx.x, t = threadIdx.x;
    const unsigned gi = b * 1024 + t;
    const unsigned v = g_count[gi];
    g_count[gi] = 0u;                      // self-clean for next invocation
    sh[t] = v;
    __syncthreads();
    for (int off = 1; off < 1024; off <<= 1) {
        unsigned u = 0;
        if (t >= off) u = sh[t - off];
        __syncthreads();
        sh[t] += u;
        __syncthreads();
    }
    g_cursor[gi] = sh[t] - v;              // exclusive within block
    if (t == 1023) g_bsum[b] = sh[t];
}

__global__ __launch_bounds__(256)
void scan_top_kernel() {
    __shared__ unsigned sh[256];
    const int t = threadIdx.x;
    const unsigned v = g_bsum[t];
    sh[t] = v;
    __syncthreads();
    for (int off = 1; off < 256; off <<= 1) {
        unsigned u = 0;
        if (t >= off) u = sh[t - off];
        __syncthreads();
        sh[t] += u;
        __syncthreads();
    }
    g_boff[t] = sh[t] - v;                 // exclusive block offsets
}

// Scatter with fused block-offset apply: slot = local_excl + boff[b/1024].
__global__ void scatter_kernel(const float* __restrict__ coords, int N) {
    int i = blockIdx.x * blockDim.x + threadIdx.x;
    if (i >= N) return;
    float x = coords[3 * i], y = coords[3 * i + 1], z = coords[3 * i + 2];
    int b = bucket_of(x, y, z);
    unsigned slot = atomicAdd(&g_cursor[b], 1u) + __ldg(&g_boff[b >> 10]);
    g_buf[slot] = make_float4(x, y, z, __int_as_float(i));
}

// ---------------------------------------------------------------------------
// Encode: proven single kernel, 64^3 bucket order, all 16 levels.
// ---------------------------------------------------------------------------
__global__ __launch_bounds__(256)
void encode_kernel(float* __restrict__ out, int N) {
    int i = blockIdx.x * blockDim.x + threadIdx.x;
    if (i >= N) return;

    const float4 pt = g_buf[i];
    const float cx = pt.x, cy = pt.y, cz = pt.z;
    const int idx = __float_as_int(pt.w);

    float4* __restrict__ out4 = reinterpret_cast<float4*>(out + (size_t)idx * 32);

    constexpr int RES[NLEV] = {16, 20, 25, 32, 40, 50, 64, 80,
                               101, 128, 161, 203, 256, 322, 406, 512};

    float4 obuf = make_float4(0.f, 0.f, 0.f, 0.f);

#pragma unroll
    for (int l = 0; l < NLEV; ++l) {
        const int res = RES[l];
        const float rm1 = (float)(res - 1);

        float px = fminf(fmaxf((cx + 1.0f) * 0.5f * rm1, 0.0f), rm1);
        float py = fminf(fmaxf((cy + 1.0f) * 0.5f * rm1, 0.0f), rm1);
        float pz = fminf(fmaxf((cz + 1.0f) * 0.5f * rm1, 0.0f), rm1);

        int ix0 = (int)px;  float wx = px - (float)ix0;
        int iy0 = (int)py;  float wy = py - (float)iy0;
        int iz0 = (int)pz;  float wz = pz - (float)iz0;
        int ix1 = min(ix0 + 1, res - 1);
        int iy1 = min(iy0 + 1, res - 1);
        int iz1 = min(iz0 + 1, res - 1);

        const float wxv0 = 1.0f - wx, wxv1 = wx;
        const float wyv0 = 1.0f - wy, wyv1 = wy;
        const float wzv0 = 1.0f - wz, wzv1 = wz;

        float2 f[8];
        float  wg[8];

        if (l == 0) {
#pragma unroll
            for (int c = 0; c < 8; ++c) {
                const int xi = (c & 4) ? ix1 : ix0;
                const int yi = (c & 2) ? iy1 : iy0;
                const int zi = (c & 1) ? iz1 : iz0;
                f[c] = __ldg(&g_dense[(xi * 16 + yi) * 16 + zi]);
                wg[c] = ((c & 4) ? wxv1 : wxv0) *
                        ((c & 2) ? wyv1 : wyv0) *
                        ((c & 1) ? wzv1 : wzv0);
            }
        } else {
            const float2* __restrict__ tbl = g_hash + (size_t)(l - 1) * TSIZE;
            const unsigned hx0 = (unsigned)ix0;  // prime 1
            const unsigned hx1 = (unsigned)ix1;
            const unsigned hy0 = (unsigned)iy0 * P1;
            const unsigned hy1 = (unsigned)iy1 * P1;
            const unsigned hz0 = (unsigned)iz0 * P2;
            const unsigned hz1 = (unsigned)iz1 * P2;
#pragma unroll
            for (int c = 0; c < 8; ++c) {
                const unsigned h = (((c & 4) ? hx1 : hx0) ^
                                    ((c & 2) ? hy1 : hy0) ^
                                    ((c & 1) ? hz1 : hz0)) & TMASK;
                f[c] = __ldg(&tbl[h]);
                wg[c] = ((c & 4) ? wxv1 : wxv0) *
                        ((c & 2) ? wyv1 : wyv0) *
                        ((c & 1) ? wzv1 : wzv0);
            }
        }

        float a0 = 0.0f, a1 = 0.0f;
#pragma unroll
        for (int c = 0; c < 8; ++c) {
            a0 = fmaf(f[c].x, wg[c], a0);
            a1 = fmaf(f[c].y, wg[c], a1);
        }

        if ((l & 1) == 0) {
            obuf.x = a0; obuf.y = a1;
        } else {
            obuf.z = a0; obuf.w = a1;
            out4[l >> 1] = obuf;
        }
    }
}

// ---------------------------------------------------------------------------
// kernel_launch:
//   stream 0: hist -> scan_part -> scan_top -> scatter(+apply)
//   stream B: repack (independent)
//   join -> encode
// ---------------------------------------------------------------------------
extern "C" void kernel_launch(void* const* d_in, const int* in_sizes, int n_in,
                              void* d_out, int out_size) {
    const float* coords = (const float*)d_in[0];
    const float* dense  = (const float*)d_in[1];
    const float* hash   = (const float*)d_in[2];
    float* out = (float*)d_out;

    const int N = in_sizes[0] / 3;
    const int nb = (N + 255) / 256;

    static cudaStream_t s_b = nullptr;
    static cudaEvent_t ev_start = nullptr, ev_repack = nullptr;
    if (s_b == nullptr) {
        cudaStreamCreateWithFlags(&s_b, cudaStreamNonBlocking);
        cudaEventCreateWithFlags(&ev_start, cudaEventDisableTiming);
        cudaEventCreateWithFlags(&ev_repack, cudaEventDisableTiming);
    }

    // Fork repack onto stream B.
    cudaEventRecord(ev_start, 0);
    cudaStreamWaitEvent(s_b, ev_start, 0);
    const unsigned repack_threads = 15u * TSIZE / 2u;
    repack_kernel<<<(repack_threads + 255u) / 256u, 256, 0, s_b>>>(dense, hash);
    cudaEventRecord(ev_repack, s_b);

    // Main branch: permutation pipeline.
    hist_kernel<<<nb, 256>>>(coords, N);
    scan_part_kernel<<<NBUCK / 1024, 1024>>>();
    scan_top_kernel<<<1, 256>>>();
    scatter_kernel<<<nb, 256>>>(coords, N);

    // Join, then encode.
    cudaStreamWaitEvent(0, ev_repack, 0);
    encode_kernel<<<nb, 256>>>(out, N);
}

// round 11
// speedup vs baseline: 1.2654x; 1.0941x over previous
#include <cuda_runtime.h>
#include <cstdint>
#include <cstddef>

#define TSIZE (1u << 18)
#define TMASK (TSIZE - 1u)
#define NLEV 16
#define P1 2654435761u
#define P2 805459861u

#define NBUCK (1u << 18)   // 64^3 buckets, Morton-coded
#define NMAX (1 << 21)

// Device-global scratch (no allocation).
// g_count zero at module load; scan re-zeroes after consuming -> zero at the
// start of every kernel_launch invocation (incl. graph replays).
__device__ __align__(16) float2 g_hash[15u * TSIZE];
__device__ __align__(16) float2 g_dense[16 * 16 * 16];
__device__ unsigned g_count[NBUCK];
__device__ unsigned g_cursor[NBUCK];
__device__ unsigned g_total;
__device__ float4   g_buf[NMAX];           // bucketed points {x,y,z,idx}

// Expand 6 low bits so they occupy every 3rd bit position.
__device__ __forceinline__ unsigned expand3(unsigned v) {
    v &= 0x3Fu;
    v = (v | (v << 8)) & 0x0300F00Fu;
    v = (v | (v << 4)) & 0x030C30C3u;
    v = (v | (v << 2)) & 0x09249249u;
    return v;
}

__device__ __forceinline__ int bucket_of(float cx, float cy, float cz) {
    unsigned bx = (unsigned)min(63, max(0, (int)((cx + 1.0f) * 32.0f)));
    unsigned by = (unsigned)min(63, max(0, (int)((cy + 1.0f) * 32.0f)));
    unsigned bz = (unsigned)min(63, max(0, (int)((cz + 1.0f) * 32.0f)));
    return (int)(expand3(bx) | (expand3(by) << 1) | (expand3(bz) << 2));
}

// ---------------------------------------------------------------------------
// Repack (stream B): tables -> feature-interleaved float2. 2 entries/thread.
// ---------------------------------------------------------------------------
__global__ void repack_kernel(const float* __restrict__ dense,
                              const float* __restrict__ hash) {
    unsigned i = blockIdx.x * blockDim.x + threadIdx.x;   // entry-pair index
    if (i < 15u * TSIZE / 2u) {
        unsigned l = i / (TSIZE / 2u);
        unsigned t = (i % (TSIZE / 2u)) * 2u;
        const float* base = hash + (size_t)l * (2u * TSIZE);
        const float2 lo = *reinterpret_cast<const float2*>(base + t);
        const float2 hi = *reinterpret_cast<const float2*>(base + TSIZE + t);
        float4 v = make_float4(lo.x, hi.x, lo.y, hi.y);
        *reinterpret_cast<float4*>(&g_hash[l * TSIZE + t]) = v;
    }
    if (i < 4096u)
        g_dense[i] = make_float2(dense[i], dense[4096u + i]);
}

// ---------------------------------------------------------------------------
// Histogram (stream A). Also resets g_total for the scan that follows.
// ---------------------------------------------------------------------------
__global__ void hist_kernel(const float* __restrict__ coords, int N) {
    int i = blockIdx.x * blockDim.x + threadIdx.x;
    if (i == 0) g_total = 0u;
    if (i >= N) return;
    int b = bucket_of(coords[3 * i], coords[3 * i + 1], coords[3 * i + 2]);
    atomicAdd(&g_count[b], 1u);
}

// ---------------------------------------------------------------------------
// Single-kernel scan: per-block inclusive scan + atomic global base.
// Slab order is atomic-arrival order (valid: bucket contiguity preserved;
// per-point output independent of g_buf ordering -> bit-exact results).
// Self-cleans g_count.
// ---------------------------------------------------------------------------
__global__ __launch_bounds__(1024)
void scan_kernel() {
    __shared__ unsigned sh[1024];
    __shared__ unsigned base;
    const int b = blockIdx.x, t = threadIdx.x;
    const unsigned gi = b * 1024 + t;
    const unsigned v = g_count[gi];
    g_count[gi] = 0u;                       // self-clean for next invocation
    sh[t] = v;
    __syncthreads();
    for (int off = 1; off < 1024; off <<= 1) {
        unsigned u = 0;
        if (t >= off) u = sh[t - off];
        __syncthreads();
        sh[t] += u;
        __syncthreads();
    }
    if (t == 1023) base = atomicAdd(&g_total, sh[1023]);
    __syncthreads();
    g_cursor[gi] = base + sh[t] - v;        // global exclusive prefix
}

__global__ void scatter_kernel(const float* __restrict__ coords, int N) {
    int i = blockIdx.x * blockDim.x + threadIdx.x;
    if (i >= N) return;
    float x = coords[3 * i], y = coords[3 * i + 1], z = coords[3 * i + 2];
    int b = bucket_of(x, y, z);
    unsigned slot = atomicAdd(&g_cursor[b], 1u);
    g_buf[slot] = make_float4(x, y, z, __int_as_float(i));
}

// ---------------------------------------------------------------------------
// Encode: proven single kernel, Morton bucket order, all 16 levels.
// ---------------------------------------------------------------------------
__global__ __launch_bounds__(256)
void encode_kernel(float* __restrict__ out, int N) {
    int i = blockIdx.x * blockDim.x + threadIdx.x;
    if (i >= N) return;

    const float4 pt = g_buf[i];
    const float cx = pt.x, cy = pt.y, cz = pt.z;
    const int idx = __float_as_int(pt.w);

    float4* __restrict__ out4 = reinterpret_cast<float4*>(out + (size_t)idx * 32);

    constexpr int RES[NLEV] = {16, 20, 25, 32, 40, 50, 64, 80,
                               101, 128, 161, 203, 256, 322, 406, 512};

    float4 obuf = make_float4(0.f, 0.f, 0.f, 0.f);

#pragma unroll
    for (int l = 0; l < NLEV; ++l) {
        const int res = RES[l];
        const float rm1 = (float)(res - 1);

        float px = fminf(fmaxf((cx + 1.0f) * 0.5f * rm1, 0.0f), rm1);
        float py = fminf(fmaxf((cy + 1.0f) * 0.5f * rm1, 0.0f), rm1);
        float pz = fminf(fmaxf((cz + 1.0f) * 0.5f * rm1, 0.0f), rm1);

        int ix0 = (int)px;  float wx = px - (float)ix0;
        int iy0 = (int)py;  float wy = py - (float)iy0;
        int iz0 = (int)pz;  float wz = pz - (float)iz0;
        int ix1 = min(ix0 + 1, res - 1);
        int iy1 = min(iy0 + 1, res - 1);
        int iz1 = min(iz0 + 1, res - 1);

        const float wxv0 = 1.0f - wx, wxv1 = wx;
        const float wyv0 = 1.0f - wy, wyv1 = wy;
        const float wzv0 = 1.0f - wz, wzv1 = wz;

        float2 f[8];
        float  wg[8];

        if (l == 0) {
#pragma unroll
            for (int c = 0; c < 8; ++c) {
                const int xi = (c & 4) ? ix1 : ix0;
                const int yi = (c & 2) ? iy1 : iy0;
                const int zi = (c & 1) ? iz1 : iz0;
                f[c] = __ldg(&g_dense[(xi * 16 + yi) * 16 + zi]);
                wg[c] = ((c & 4) ? wxv1 : wxv0) *
                        ((c & 2) ? wyv1 : wyv0) *
                        ((c & 1) ? wzv1 : wzv0);
            }
        } else {
            const float2* __restrict__ tbl = g_hash + (size_t)(l - 1) * TSIZE;
            const unsigned hx0 = (unsigned)ix0;  // prime 1
            const unsigned hx1 = (unsigned)ix1;
            const unsigned hy0 = (unsigned)iy0 * P1;
            const unsigned hy1 = (unsigned)iy1 * P1;
            const unsigned hz0 = (unsigned)iz0 * P2;
            const unsigned hz1 = (unsigned)iz1 * P2;
#pragma unroll
            for (int c = 0; c < 8; ++c) {
                const unsigned h = (((c & 4) ? hx1 : hx0) ^
                                    ((c & 2) ? hy1 : hy0) ^
                                    ((c & 1) ? hz1 : hz0)) & TMASK;
                f[c] = __ldg(&tbl[h]);
                wg[c] = ((c & 4) ? wxv1 : wxv0) *
                        ((c & 2) ? wyv1 : wyv0) *
                        ((c & 1) ? wzv1 : wzv0);
            }
        }

        float a0 = 0.0f, a1 = 0.0f;
#pragma unroll
        for (int c = 0; c < 8; ++c) {
            a0 = fmaf(f[c].x, wg[c], a0);
            a1 = fmaf(f[c].y, wg[c], a1);
        }

        if ((l & 1) == 0) {
            obuf.x = a0; obuf.y = a1;
        } else {
            obuf.z = a0; obuf.w = a1;
            out4[l >> 1] = obuf;
        }
    }
}

// ---------------------------------------------------------------------------
// kernel_launch:
//   stream 0: hist -> scan -> scatter -> encode
//   stream B: repack (independent, joins before encode)
// ---------------------------------------------------------------------------
extern "C" void kernel_launch(void* const* d_in, const int* in_sizes, int n_in,
                              void* d_out, int out_size) {
    const float* coords = (const float*)d_in[0];
    const float* dense  = (const float*)d_in[1];
    const float* hash   = (const float*)d_in[2];
    float* out = (float*)d_out;

    const int N = in_sizes[0] / 3;
    const int nb = (N + 255) / 256;

    static cudaStream_t s_b = nullptr;
    static cudaEvent_t ev_start = nullptr, ev_repack = nullptr;
    if (s_b == nullptr) {
        cudaStreamCreateWithFlags(&s_b, cudaStreamNonBlocking);
        cudaEventCreateWithFlags(&ev_start, cudaEventDisableTiming);
        cudaEventCreateWithFlags(&ev_repack, cudaEventDisableTiming);
    }

    // Fork repack onto stream B.
    cudaEventRecord(ev_start, 0);
    cudaStreamWaitEvent(s_b, ev_start, 0);
    const unsigned repack_threads = 15u * TSIZE / 2u;
    repack_kernel<<<(repack_threads + 255u) / 256u, 256, 0, s_b>>>(dense, hash);
    cudaEventRecord(ev_repack, s_b);

    // Main branch: permutation pipeline.
    hist_kernel<<<nb, 256>>>(coords, N);
    scan_kernel<<<NBUCK / 1024, 1024>>>();
    scatter_kernel<<<nb, 256>>>(coords, N);

    // Join, then encode.
    cudaStreamWaitEvent(0, ev_repack, 0);
    encode_kernel<<<nb, 256>>>(out, N);
}